// round 3
// baseline (speedup 1.0000x reference)
#include <cuda_runtime.h>
#include <cuda_fp16.h>

#define T_STEPS 4096
#define HID     2048
#define DIN     66
#define PRE     64
#define OUT_T   (T_STEPS - PRE)   // 4032
#define G4      8192              // 4*HID gate rows
#define NBLK    128
#define NTHR    512
#define UNITS   16                // hidden units per block per layer
#define KA      2304              // padded K for layer1: 2048 + 66 -> 9*256
#define KB      4096              // layer2: [h1 ; h2]
#define NIT_A   9
#define NIT_B   16
#define OB_ROWS 4

// ---------------- static device scratch (no allocations allowed) ----------------
__device__ __half g_W1[(size_t)G4 * KA];        // 37.7 MB  [W_hh1 | W_ih1 | 0] fp16
__device__ __half g_W2[(size_t)G4 * KB];        // 67.1 MB  [W_ih2 | W_hh2]    fp16
__device__ float  g_b1[G4];
__device__ float  g_b2[G4];
__device__ __half g_xh[T_STEPS * DIN];
__device__ __half g_h1h[2][HID];                // parity double-buffered h1 (half)
__device__ __half g_h2h[2][HID];                // parity double-buffered h2 (half)
__device__ float  g_hist[(size_t)T_STEPS * HID];// h2 history (fp32) for output GEMM
__device__ unsigned g_cnt;                      // grid barrier counter (monotonic)

// ---------------- prep kernels ----------------
__global__ void prep_w1(const float* __restrict__ Whh1, const float* __restrict__ Wih1) {
    size_t i = (size_t)blockIdx.x * blockDim.x + threadIdx.x;
    if (i >= (size_t)G4 * KA) return;
    int j = (int)(i / KA);
    int c = (int)(i % KA);
    float v = 0.f;
    if (c < HID)            v = Whh1[(size_t)j * HID + c];
    else if (c < HID + DIN) v = Wih1[(size_t)j * DIN + (c - HID)];
    g_W1[i] = __float2half(v);
}

__global__ void prep_w2(const float* __restrict__ Wih2, const float* __restrict__ Whh2) {
    size_t i = (size_t)blockIdx.x * blockDim.x + threadIdx.x;
    if (i >= (size_t)G4 * KB) return;
    int j = (int)(i / KB);
    int c = (int)(i % KB);
    float v = (c < HID) ? Wih2[(size_t)j * HID + c]
                        : Whh2[(size_t)j * HID + (c - HID)];
    g_W2[i] = __float2half(v);
}

__global__ void prep_misc(const float* __restrict__ y,
                          const float* __restrict__ bi1, const float* __restrict__ bh1,
                          const float* __restrict__ bi2, const float* __restrict__ bh2) {
    int i = blockIdx.x * blockDim.x + threadIdx.x;
    if (i < T_STEPS * DIN) g_xh[i] = __float2half(y[i]);
    if (i < G4) { g_b1[i] = bi1[i] + bh1[i]; g_b2[i] = bi2[i] + bh2[i]; }
    if (i < HID) {
        __half z = __float2half(0.f);
        g_h1h[0][i] = z; g_h1h[1][i] = z;
        g_h2h[0][i] = z; g_h2h[1][i] = z;
    }
    if (i == 0) g_cnt = 0u;
}

// ---------------- math helpers ----------------
__device__ __forceinline__ float sigmoidf_(float x) {
    return 1.f / (1.f + __expf(-x));
}
__device__ __forceinline__ float tanhf_(float x) {
    float e = __expf(-2.f * fabsf(x));      // underflows to 0 for large |x| -> r = 1
    float r = (1.f - e) / (1.f + e);
    return (x < 0.f) ? -r : r;
}

// 64-row matvec: warp w owns rows 4w..4w+3; lane strips of 8 halves.
// Products in half2, chunk(8)-accumulated, flushed to fp32 every iteration.
template<int NIT>
__device__ __forceinline__ void matvec64(const __half* __restrict__ W, int ldk,
                                         const __half* vec,
                                         const float* __restrict__ bias,
                                         float* gates, int base) {
    const int tid  = threadIdx.x;
    const int warp = tid >> 5;
    const int lane = tid & 31;
    const int k0   = warp * 4;
    const uint4* vs = (const uint4*)vec;

    size_t roff[4];
    int    jrow[4];
#pragma unroll
    for (int r = 0; r < 4; ++r) {
        int k = k0 + r;
        int j = ((k >> 4) * HID) + base + (k & 15);  // gate g = k/16, unit u = k%16
        jrow[r] = j;
        roff[r] = (size_t)j * ldk + lane * 8;
    }

    float s0 = 0.f, s1 = 0.f, s2 = 0.f, s3 = 0.f;
#pragma unroll
    for (int it = 0; it < NIT; ++it) {
        uint4 hv = vs[it * 32 + lane];
        __half2 h0 = *(__half2*)&hv.x;
        __half2 h1 = *(__half2*)&hv.y;
        __half2 h2 = *(__half2*)&hv.z;
        __half2 h3 = *(__half2*)&hv.w;
#define ROWSTEP(R, ACC)                                                     \
        {                                                                   \
            uint4 wv = *(const uint4*)(W + roff[R] + it * 256);             \
            __half2 a = __hmul2(*(__half2*)&wv.x, h0);                      \
            a = __hfma2(*(__half2*)&wv.y, h1, a);                           \
            a = __hfma2(*(__half2*)&wv.z, h2, a);                           \
            a = __hfma2(*(__half2*)&wv.w, h3, a);                           \
            float2 f = __half22float2(a);                                   \
            ACC += f.x; ACC += f.y;                                         \
        }
        ROWSTEP(0, s0) ROWSTEP(1, s1) ROWSTEP(2, s2) ROWSTEP(3, s3)
#undef ROWSTEP
    }

    float sums[4] = { s0, s1, s2, s3 };
#pragma unroll
    for (int r = 0; r < 4; ++r) {
        float v = sums[r];
#pragma unroll
        for (int o = 16; o > 0; o >>= 1) v += __shfl_xor_sync(0xffffffffu, v, o);
        if (lane == 0) gates[k0 + r] = v + bias[jrow[r]];
    }
}

// ---------------- main persistent recurrent kernel ----------------
__global__ void __launch_bounds__(NTHR, 1) lstm_main() {
    __shared__ __align__(16) __half vA[KA];
    __shared__ __align__(16) __half vB[KB];
    __shared__ float gates[64];
    __shared__ float c1s[UNITS], c2s[UNITS];

    const int tid  = threadIdx.x;
    const int base = blockIdx.x * UNITS;

    if (tid < UNITS) { c1s[tid] = 0.f; c2s[tid] = 0.f; }
    for (int i = HID + DIN + tid; i < KA; i += NTHR) vA[i] = __float2half(0.f); // pad tail once
    unsigned bar_target = 0;
    __syncthreads();

    for (int t = 0; t < T_STEPS; ++t) {
        const int par = t & 1, prev = par ^ 1;

        // ---- fill layer-1 vector: [h1(t-1) ; x_t ; 0] ----
        ((uint2*)vA)[tid] = __ldcg(((const uint2*)g_h1h[prev]) + tid);  // 2048 halves
        if (tid < DIN) vA[HID + tid] = g_xh[t * DIN + tid];
        __syncthreads();

        matvec64<NIT_A>(g_W1, KA, vA, g_b1, gates, base);
        __syncthreads();

        if (tid < UNITS) {
            float gi = sigmoidf_(gates[tid]);
            float gf = sigmoidf_(gates[16 + tid]);
            float gg = tanhf_(gates[32 + tid]);
            float go = sigmoidf_(gates[48 + tid]);
            float c  = gf * c1s[tid] + gi * gg;
            c1s[tid] = c;
            float h  = go * tanhf_(c);
            __stcg(&g_h1h[par][base + tid], __float2half(h));
        }

        // ---- single grid barrier per step ----
        __syncthreads();
        bar_target += NBLK;
        if (tid == 0) {
            __threadfence();
            atomicAdd(&g_cnt, 1u);
            while (*(volatile unsigned*)&g_cnt < bar_target) { }
            __threadfence();
        }
        __syncthreads();

        // ---- fill layer-2 vector: [h1(t) ; h2(t-1)] ----
        ((uint2*)vB)[tid]       = __ldcg(((const uint2*)g_h1h[par]) + tid);
        ((uint2*)vB)[512 + tid] = __ldcg(((const uint2*)g_h2h[prev]) + tid);
        __syncthreads();

        matvec64<NIT_B>(g_W2, KB, vB, g_b2, gates, base);
        __syncthreads();

        if (tid < UNITS) {
            float gi = sigmoidf_(gates[tid]);
            float gf = sigmoidf_(gates[16 + tid]);
            float gg = tanhf_(gates[32 + tid]);
            float go = sigmoidf_(gates[48 + tid]);
            float c  = gf * c2s[tid] + gi * gg;
            c2s[tid] = c;
            float h  = go * tanhf_(c);
            __stcg(&g_h2h[par][base + tid], __float2half(h));
            __stcs(&g_hist[(size_t)t * HID + base + tid], h);   // evict-first: protect L2 weights
        }
        // no second barrier needed: h2(t) publication is ordered by barrier(t+1),
        // whose arrival requires every block to have finished layer-1(t+1).
    }
}

// ---------------- deferred output projection: out[t] = h2[t] @ W_lin^T + b_lin ----------------
__global__ void out_kernel(const float* __restrict__ Wlin,
                           const float* __restrict__ blin,
                           float* __restrict__ out) {
    __shared__ float h2s[OB_ROWS][HID];   // 32 KB
    const int tid = threadIdx.x, warp = tid >> 5, lane = tid & 31;
    const int t0  = PRE + blockIdx.x * OB_ROWS;

    const float4* src = (const float4*)&g_hist[(size_t)t0 * HID];
    float4*       dst = (float4*)&h2s[0][0];
    for (int i = tid; i < OB_ROWS * HID / 4; i += 256) dst[i] = src[i];
    __syncthreads();

    for (int rr = 0; rr < OB_ROWS; ++rr) {
        for (int j = warp; j < DIN; j += 8) {
            const float* wr = Wlin + (size_t)j * HID;
            float s = 0.f;
#pragma unroll 8
            for (int c = lane; c < HID; c += 32) s += wr[c] * h2s[rr][c];
#pragma unroll
            for (int o = 16; o > 0; o >>= 1) s += __shfl_xor_sync(0xffffffffu, s, o);
            if (lane == 0)
                out[(size_t)(blockIdx.x * OB_ROWS + rr) * DIN + j] = s + blin[j];
        }
    }
}

// ---------------- launch ----------------
extern "C" void kernel_launch(void* const* d_in, const int* in_sizes, int n_in,
                              void* d_out, int out_size) {
    const float* y    = (const float*)d_in[0];
    const float* Wih1 = (const float*)d_in[1];
    const float* Whh1 = (const float*)d_in[2];
    const float* bih1 = (const float*)d_in[3];
    const float* bhh1 = (const float*)d_in[4];
    const float* Wih2 = (const float*)d_in[5];
    const float* Whh2 = (const float*)d_in[6];
    const float* bih2 = (const float*)d_in[7];
    const float* bhh2 = (const float*)d_in[8];
    const float* Wlin = (const float*)d_in[9];
    const float* blin = (const float*)d_in[10];
    float* out = (float*)d_out;

    prep_misc<<<1056, 256>>>(y, bih1, bhh1, bih2, bhh2);
    prep_w1<<<(unsigned)(((size_t)G4 * KA + 255) / 256), 256>>>(Whh1, Wih1);
    prep_w2<<<(unsigned)(((size_t)G4 * KB + 255) / 256), 256>>>(Wih2, Whh2);
    lstm_main<<<NBLK, NTHR>>>();
    out_kernel<<<OUT_T / OB_ROWS, 256>>>(Wlin, blin, out);
}

// round 4
// speedup vs baseline: 1.2529x; 1.2529x over previous
#include <cuda_runtime.h>
#include <cuda_fp16.h>

#define T_STEPS 4096
#define HID     2048
#define DIN     66
#define PRE     64
#define OUT_T   (T_STEPS - PRE)   // 4032
#define G4      8192              // 4*HID gate rows
#define NBLK    128
#define NTHR    512
#define UNITS   16                // hidden units per block per layer
#define KB      4096              // layer2 K: [h1 ; h2]
#define NIT_A   8                 // 2048 / 256
#define NIT_B   16                // 4096 / 256
#define PK      1536              // pinned columns of W2 per row (in SMEM)
#define PIN_IT  6                 // PK / 256
#define OB_ROWS 4

#define PIN_BYTES  (64 * PK * 2)                    // 196608
#define DYN_BYTES  (PIN_BYTES + HID * 2 + KB * 2)   // + vA(4KB) + vB(8KB) = 208896

// ---------------- static device scratch (no allocations allowed) ----------------
__device__ __half g_W1[(size_t)G4 * HID];       // 33.5 MB  W_hh1 fp16
__device__ __half g_W2[(size_t)G4 * KB];        // 67.1 MB  [W_ih2 | W_hh2] fp16
__device__ float  g_b2[G4];
__device__ float  g_gx[(size_t)T_STEPS * G4];   // 134 MB: x@W_ih1^T + b1, block-permuted
__device__ __half g_h1h[2][HID];                // parity double-buffered h1 (half)
__device__ __half g_h2h[2][HID];                // parity double-buffered h2 (half)
__device__ float  g_hist[(size_t)T_STEPS * HID];// h2 history (fp32) for output GEMM
__device__ unsigned g_cnt;                      // grid barrier counter (monotonic)

// row index within block (k=0..63) -> global gate row j
__device__ __forceinline__ int row_j(int k, int base) {
    return ((k >> 4) * HID) + base + (k & 15);
}

// ---------------- prep kernels ----------------
__global__ void prep_w1(const float* __restrict__ Whh1) {
    size_t i = (size_t)blockIdx.x * blockDim.x + threadIdx.x;
    if (i < (size_t)G4 * HID) g_W1[i] = __float2half(Whh1[i]);
}

__global__ void prep_w2(const float* __restrict__ Wih2, const float* __restrict__ Whh2) {
    size_t i = (size_t)blockIdx.x * blockDim.x + threadIdx.x;
    if (i >= (size_t)G4 * KB) return;
    int j = (int)(i / KB);
    int c = (int)(i % KB);
    float v = (c < HID) ? Wih2[(size_t)j * HID + c]
                        : Whh2[(size_t)j * HID + (c - HID)];
    g_W2[i] = __float2half(v);
}

__global__ void prep_misc(const float* __restrict__ bi2, const float* __restrict__ bh2) {
    int i = blockIdx.x * blockDim.x + threadIdx.x;
    if (i < G4) g_b2[i] = bi2[i] + bh2[i];
    if (i < HID) {
        __half z = __float2half(0.f);
        g_h1h[0][i] = z; g_h1h[1][i] = z;
        g_h2h[0][i] = z; g_h2h[1][i] = z;
    }
    if (i == 0) g_cnt = 0u;
}

// gates_x[t, blk, k] = b1[j] + sum_c y[t,c] * W_ih1[j,c]   (block-local row order k)
__global__ void prep_gx(const float* __restrict__ y, const float* __restrict__ Wih1,
                        const float* __restrict__ bi1, const float* __restrict__ bh1) {
    __shared__ float sW[64][DIN];
    __shared__ float sb[64];
    const int b = blockIdx.x, base = b * UNITS;
    for (int idx = threadIdx.x; idx < 64 * DIN; idx += NTHR) {
        int k = idx / DIN, c = idx % DIN;
        sW[k][c] = Wih1[(size_t)row_j(k, base) * DIN + c];
    }
    if (threadIdx.x < 64) {
        int j = row_j(threadIdx.x, base);
        sb[threadIdx.x] = bi1[j] + bh1[j];
    }
    __syncthreads();
    for (int t = threadIdx.x; t < T_STEPS; t += NTHR) {
        float xv[DIN];
#pragma unroll
        for (int c = 0; c < DIN; ++c) xv[c] = y[(size_t)t * DIN + c];
        float* outp = &g_gx[((size_t)t * NBLK + b) * 64];
        for (int k = 0; k < 64; ++k) {
            float s = sb[k];
#pragma unroll
            for (int c = 0; c < DIN; ++c) s += sW[k][c] * xv[c];
            outp[k] = s;
        }
    }
}

// ---------------- math helpers ----------------
__device__ __forceinline__ float sigmoidf_(float x) { return 1.f / (1.f + __expf(-x)); }
__device__ __forceinline__ float tanhf_(float x) {
    float e = __expf(-2.f * fabsf(x));
    float r = (1.f - e) / (1.f + e);
    return (x < 0.f) ? -r : r;
}

#define ROWSTEP(WPTR, ACC)                                                  \
    {                                                                       \
        uint4 wv = *(const uint4*)(WPTR);                                   \
        __half2 a = __hmul2(*(__half2*)&wv.x, h0);                          \
        a = __hfma2(*(__half2*)&wv.y, h1, a);                               \
        a = __hfma2(*(__half2*)&wv.z, h2, a);                               \
        a = __hfma2(*(__half2*)&wv.w, h3, a);                               \
        float2 f = __half22float2(a);                                       \
        ACC += f.x; ACC += f.y;                                             \
    }

// layer-1 matvec: 64 rows over K=2048, gate base preloaded from g_gx (bias folded)
__device__ __forceinline__ void matvecA(const __half* vec, const float* __restrict__ gx,
                                        float* gates, int base) {
    const int tid = threadIdx.x, warp = tid >> 5, lane = tid & 31;
    const int k0 = warp * 4;
    const uint4* vs = (const uint4*)vec;

    float gxv[4];
    size_t roff[4];
#pragma unroll
    for (int r = 0; r < 4; ++r)
        roff[r] = (size_t)row_j(k0 + r, base) * HID + lane * 8;
    if (lane == 0) {
#pragma unroll
        for (int r = 0; r < 4; ++r) gxv[r] = __ldcs(gx + k0 + r);
    }

    float s0 = 0.f, s1 = 0.f, s2 = 0.f, s3 = 0.f;
#pragma unroll
    for (int it = 0; it < NIT_A; ++it) {
        uint4 hv = vs[it * 32 + lane];
        __half2 h0 = *(__half2*)&hv.x;
        __half2 h1 = *(__half2*)&hv.y;
        __half2 h2 = *(__half2*)&hv.z;
        __half2 h3 = *(__half2*)&hv.w;
        ROWSTEP(g_W1 + roff[0] + it * 256, s0)
        ROWSTEP(g_W1 + roff[1] + it * 256, s1)
        ROWSTEP(g_W1 + roff[2] + it * 256, s2)
        ROWSTEP(g_W1 + roff[3] + it * 256, s3)
    }
    float sums[4] = { s0, s1, s2, s3 };
#pragma unroll
    for (int r = 0; r < 4; ++r) {
        float v = sums[r];
#pragma unroll
        for (int o = 16; o > 0; o >>= 1) v += __shfl_xor_sync(0xffffffffu, v, o);
        if (lane == 0) gates[k0 + r] = v + gxv[r];
    }
}

// layer-2 matvec: 64 rows over K=4096; first PIN_IT strips come from SMEM-pinned W2
__device__ __forceinline__ void matvecB(const __half* __restrict__ sW2, const __half* vec,
                                        float* gates, int base) {
    const int tid = threadIdx.x, warp = tid >> 5, lane = tid & 31;
    const int k0 = warp * 4;
    const uint4* vs = (const uint4*)vec;

    size_t roff[4];
    int    jrow[4];
#pragma unroll
    for (int r = 0; r < 4; ++r) {
        jrow[r] = row_j(k0 + r, base);
        roff[r] = (size_t)jrow[r] * KB + lane * 8;
    }
    const __half* spin = sW2 + (size_t)k0 * PK + lane * 8;

    float s0 = 0.f, s1 = 0.f, s2 = 0.f, s3 = 0.f;
#pragma unroll
    for (int it = 0; it < PIN_IT; ++it) {
        uint4 hv = vs[it * 32 + lane];
        __half2 h0 = *(__half2*)&hv.x;
        __half2 h1 = *(__half2*)&hv.y;
        __half2 h2 = *(__half2*)&hv.z;
        __half2 h3 = *(__half2*)&hv.w;
        ROWSTEP(spin + 0 * PK + it * 256, s0)
        ROWSTEP(spin + 1 * PK + it * 256, s1)
        ROWSTEP(spin + 2 * PK + it * 256, s2)
        ROWSTEP(spin + 3 * PK + it * 256, s3)
    }
#pragma unroll
    for (int it = PIN_IT; it < NIT_B; ++it) {
        uint4 hv = vs[it * 32 + lane];
        __half2 h0 = *(__half2*)&hv.x;
        __half2 h1 = *(__half2*)&hv.y;
        __half2 h2 = *(__half2*)&hv.z;
        __half2 h3 = *(__half2*)&hv.w;
        ROWSTEP(g_W2 + roff[0] + it * 256, s0)
        ROWSTEP(g_W2 + roff[1] + it * 256, s1)
        ROWSTEP(g_W2 + roff[2] + it * 256, s2)
        ROWSTEP(g_W2 + roff[3] + it * 256, s3)
    }
    float sums[4] = { s0, s1, s2, s3 };
#pragma unroll
    for (int r = 0; r < 4; ++r) {
        float v = sums[r];
#pragma unroll
        for (int o = 16; o > 0; o >>= 1) v += __shfl_xor_sync(0xffffffffu, v, o);
        if (lane == 0) gates[k0 + r] = v + g_b2[jrow[r]];
    }
}

// ---------------- main persistent recurrent kernel ----------------
__global__ void __launch_bounds__(NTHR, 1) lstm_main() {
    extern __shared__ __align__(16) unsigned char dynsmem[];
    __half* sW2 = (__half*)dynsmem;                       // 64 x PK pinned W2 slice
    __half* vA  = (__half*)(dynsmem + PIN_BYTES);         // 2048 halves
    __half* vB  = vA + HID;                               // 4096 halves
    __shared__ float gates[64];
    __shared__ float c1s[UNITS], c2s[UNITS];

    const int tid  = threadIdx.x;
    const int base = blockIdx.x * UNITS;

    if (tid < UNITS) { c1s[tid] = 0.f; c2s[tid] = 0.f; }

    // ---- one-time: pin first PK columns of this block's 64 W2 rows into SMEM ----
    {
        const int PK8 = PK / 8;                           // uint4 per row
        for (int idx = tid; idx < 64 * PK8; idx += NTHR) {
            int k = idx / PK8, c8 = idx % PK8;
            ((uint4*)(sW2 + (size_t)k * PK))[c8] =
                *(const uint4*)(g_W2 + (size_t)row_j(k, base) * KB + c8 * 8);
        }
    }
    unsigned bar_target = 0;
    __syncthreads();

    for (int t = 0; t < T_STEPS; ++t) {
        const int par = t & 1, prev = par ^ 1;

        // ---- layer 1: vA = h1(t-1) ----
        ((uint2*)vA)[tid] = __ldcg(((const uint2*)g_h1h[prev]) + tid);
        __syncthreads();

        matvecA(vA, &g_gx[((size_t)t * NBLK + blockIdx.x) * 64], gates, base);

        // prefetch h2(t-1) half of vB (already synchronized by barrier(t-1))
        ((uint2*)vB)[512 + tid] = __ldcg(((const uint2*)g_h2h[prev]) + tid);
        __syncthreads();

        if (tid < UNITS) {
            float gi = sigmoidf_(gates[tid]);
            float gf = sigmoidf_(gates[16 + tid]);
            float gg = tanhf_(gates[32 + tid]);
            float go = sigmoidf_(gates[48 + tid]);
            float c  = gf * c1s[tid] + gi * gg;
            c1s[tid] = c;
            float h  = go * tanhf_(c);
            __stcg(&g_h1h[par][base + tid], __float2half(h));
        }

        // ---- single grid barrier per step ----
        __syncthreads();
        bar_target += NBLK;
        if (tid == 0) {
            __threadfence();
            atomicAdd(&g_cnt, 1u);
            while (*(volatile unsigned*)&g_cnt < bar_target) { }
            __threadfence();
        }
        __syncthreads();

        // ---- layer 2: vB = [h1(t) ; h2(t-1)] (h2 part already filled) ----
        ((uint2*)vB)[tid] = __ldcg(((const uint2*)g_h1h[par]) + tid);
        __syncthreads();

        matvecB(sW2, vB, gates, base);
        __syncthreads();

        if (tid < UNITS) {
            float gi = sigmoidf_(gates[tid]);
            float gf = sigmoidf_(gates[16 + tid]);
            float gg = tanhf_(gates[32 + tid]);
            float go = sigmoidf_(gates[48 + tid]);
            float c  = gf * c2s[tid] + gi * gg;
            c2s[tid] = c;
            float h  = go * tanhf_(c);
            __stcg(&g_h2h[par][base + tid], __float2half(h));
            __stcs(&g_hist[(size_t)t * HID + base + tid], h);
        }
        // h2(t) publication is ordered by barrier(t+1).
    }
}

// ---------------- deferred output projection ----------------
__global__ void out_kernel(const float* __restrict__ Wlin,
                           const float* __restrict__ blin,
                           float* __restrict__ out) {
    __shared__ float h2s[OB_ROWS][HID];
    const int tid = threadIdx.x, warp = tid >> 5, lane = tid & 31;
    const int t0  = PRE + blockIdx.x * OB_ROWS;

    const float4* src = (const float4*)&g_hist[(size_t)t0 * HID];
    float4*       dst = (float4*)&h2s[0][0];
    for (int i = tid; i < OB_ROWS * HID / 4; i += 256) dst[i] = src[i];
    __syncthreads();

    for (int rr = 0; rr < OB_ROWS; ++rr) {
        for (int j = warp; j < DIN; j += 8) {
            const float* wr = Wlin + (size_t)j * HID;
            float s = 0.f;
#pragma unroll 8
            for (int c = lane; c < HID; c += 32) s += wr[c] * h2s[rr][c];
#pragma unroll
            for (int o = 16; o > 0; o >>= 1) s += __shfl_xor_sync(0xffffffffu, s, o);
            if (lane == 0)
                out[(size_t)(blockIdx.x * OB_ROWS + rr) * DIN + j] = s + blin[j];
        }
    }
}

// ---------------- launch ----------------
extern "C" void kernel_launch(void* const* d_in, const int* in_sizes, int n_in,
                              void* d_out, int out_size) {
    const float* y    = (const float*)d_in[0];
    const float* Wih1 = (const float*)d_in[1];
    const float* Whh1 = (const float*)d_in[2];
    const float* bih1 = (const float*)d_in[3];
    const float* bhh1 = (const float*)d_in[4];
    const float* Wih2 = (const float*)d_in[5];
    const float* Whh2 = (const float*)d_in[6];
    const float* bih2 = (const float*)d_in[7];
    const float* bhh2 = (const float*)d_in[8];
    const float* Wlin = (const float*)d_in[9];
    const float* blin = (const float*)d_in[10];
    float* out = (float*)d_out;

    static int smem_set = 0;
    if (!smem_set) {
        cudaFuncSetAttribute(lstm_main, cudaFuncAttributeMaxDynamicSharedMemorySize, DYN_BYTES);
        smem_set = 1;
    }

    prep_misc<<<32, 256>>>(bih2, bhh2);
    prep_w1<<<(unsigned)(((size_t)G4 * HID + 255) / 256), 256>>>(Whh1);
    prep_w2<<<(unsigned)(((size_t)G4 * KB + 255) / 256), 256>>>(Wih2, Whh2);
    prep_gx<<<NBLK, NTHR>>>(y, Wih1, bih1, bhh1);
    lstm_main<<<NBLK, NTHR, DYN_BYTES>>>();
    out_kernel<<<OUT_T / OB_ROWS, 256>>>(Wlin, blin, out);
}